// round 17
// baseline (speedup 1.0000x reference)
#include <cuda_runtime.h>
#include <cstdint>

#define NW 12
#define DIM 4096       // 2^12
#define INDIM 256
#define NT 256

// ---- packed f32x2 ops (sm_103a) ----
__device__ __forceinline__ uint64_t addx2(uint64_t a, uint64_t b) {
    uint64_t r; asm("add.rn.f32x2 %0, %1, %2;" : "=l"(r) : "l"(a), "l"(b)); return r;
}
__device__ __forceinline__ uint64_t subx2(uint64_t a, uint64_t b) {
    uint64_t r; asm("sub.rn.f32x2 %0, %1, %2;" : "=l"(r) : "l"(a), "l"(b)); return r;
}
__device__ __forceinline__ uint64_t mulx2(uint64_t a, uint64_t b) {
    uint64_t r; asm("mul.rn.f32x2 %0, %1, %2;" : "=l"(r) : "l"(a), "l"(b)); return r;
}
__device__ __forceinline__ uint64_t packx2(float lo, float hi) {
    uint64_t r; asm("mov.b64 %0, {%1, %2};" : "=l"(r) : "f"(lo), "f"(hi)); return r;
}
__device__ __forceinline__ void unpackx2(float& lo, float& hi, uint64_t v) {
    asm("mov.b64 {%0, %1}, %2;" : "=f"(lo), "=f"(hi) : "l"(v));
}
__device__ __forceinline__ float hsum(uint64_t v) {
    float lo, hi; unpackx2(lo, hi, v); return lo + hi;
}

// In-register 4-level WHT butterflies on packed (cos,sin) pairs
__device__ __forceinline__ void wht16p(uint64_t U[16]) {
#pragma unroll
    for (int k = 0; k < 4; k++) {
        const int m = 1 << k;
#pragma unroll
        for (int i = 0; i < 16; i++) {
            if (!(i & m)) {
                uint64_t a = U[i], b = U[i | m];
                U[i]     = addx2(a, b);
                U[i | m] = subx2(a, b);
            }
        }
    }
}

// Sparse phase evaluation -> packed unit vectors U[16] (cos, sin)
__device__ __forceinline__ void phase_to_unit(const float* __restrict__ cvp,
                                              uint32_t tid, const uint32_t wArr[4],
                                              uint64_t U[16]) {
    float B[16];
#pragma unroll
    for (int n = 0; n < 16; n++) B[n] = 0.f;
    const int Pm[4] = {0x111, 0x333, 0x555, 0xFFF};
#pragma unroll
    for (int v = 0; v < 10; v++) {
#pragma unroll
        for (int i = 0; i < 4; i++) {
            const int m   = (Pm[i] << v) & 0xFFF;   // compile-time constant
            const int mlo = m & 15;
            float a = cvp[v * 4 + i];                // uniform LDS broadcast
            uint32_t sgn = (wArr[i] << (31 - v)) & 0x80000000u;
            B[mlo] += __int_as_float(__float_as_int(a) ^ sgn);
        }
    }
    {   // merged high-wire terms -> bucket 0; signs from tid bits 6/7
        const uint32_t u = tid ^ (tid >> 1);
        float a = cvp[40];
        B[0] += __int_as_float(__float_as_int(a) ^ ((tid << 25) & 0x80000000u));
        a = cvp[41];
        B[0] += __int_as_float(__float_as_int(a) ^ ((u << 25) & 0x80000000u));
        a = cvp[42];
        B[0] += __int_as_float(__float_as_int(a) ^ ((tid << 24) & 0x80000000u));
    }
    // WHT16 over B: level 0 scalar + pack pairs, levels 1-3 packed
    uint64_t C[8];
#pragma unroll
    for (int j = 0; j < 8; j++)
        C[j] = packx2(B[2 * j] + B[2 * j + 1], B[2 * j] - B[2 * j + 1]);
#pragma unroll
    for (int k = 0; k < 3; k++) {
        const int m = 1 << k;
#pragma unroll
        for (int j = 0; j < 8; j++) {
            if (!(j & m)) {
                uint64_t a = C[j], bb = C[j | m];
                C[j]     = addx2(a, bb);
                C[j | m] = subx2(a, bb);
            }
        }
    }
#pragma unroll
    for (int j = 0; j < 8; j++) {
        float blo, bhi; unpackx2(blo, bhi, C[j]);
        float sv, cvv;
        __sincosf(blo, &sv, &cvv); U[2 * j]     = packx2(cvv, sv);
        __sincosf(bhi, &sv, &cvv); U[2 * j + 1] = packx2(cvv, sv);
    }
}

// Parseval partial tree: psum, T8..T11 from U
__device__ __forceinline__ void parseval(const uint64_t U[16], float& psum,
                                         float& T8, float& T9, float& T10, float& T11) {
    uint64_t sj[8], dj[8];
#pragma unroll
    for (int j = 0; j < 8; j++) {
        uint64_t q0 = mulx2(U[2 * j], U[2 * j]);
        uint64_t q1 = mulx2(U[2 * j + 1], U[2 * j + 1]);
        sj[j] = addx2(q0, q1);
        dj[j] = subx2(q0, q1);
    }
    uint64_t T8p = addx2(addx2(addx2(dj[0], dj[1]), addx2(dj[2], dj[3])),
                         addx2(addx2(dj[4], dj[5]), addx2(dj[6], dj[7])));
    uint64_t u0 = addx2(sj[0], sj[1]), u1 = addx2(sj[2], sj[3]);
    uint64_t u2 = addx2(sj[4], sj[5]), u3 = addx2(sj[6], sj[7]);
    uint64_t v0 = subx2(sj[0], sj[1]), v1 = subx2(sj[2], sj[3]);
    uint64_t v2 = subx2(sj[4], sj[5]), v3 = subx2(sj[6], sj[7]);
    uint64_t T9p  = addx2(addx2(v0, v1), addx2(v2, v3));
    uint64_t p0 = addx2(u0, u1), p1 = addx2(u2, u3);
    uint64_t T10p = addx2(subx2(u0, u1), subx2(u2, u3));
    psum = hsum(addx2(p0, p1));
    T11  = hsum(subx2(p0, p1));
    T8   = hsum(T8p);
    T9   = hsum(T9p);
    T10  = hsum(T10p);
}

__global__ void __launch_bounds__(NT, 3)
sim_kernel(const float* __restrict__ x, const float* __restrict__ W,
           const float* __restrict__ params, float* __restrict__ out)
{
    extern __shared__ __align__(16) uint64_t cs[];   // [2 * DIM] packed buffers
    uint64_t* csA = cs;
    uint64_t* csB = cs + DIM;
    __shared__ float red[2][NW * 2];
    __shared__ float cv[2][44];
    __shared__ float wA[2][5 * 8];
    __shared__ float w0[2][8];
    __shared__ float wT[2][4 * 32];

    const int tid  = threadIdx.x;
    const int bA   = blockIdx.x * 2;
    const int bB   = bA + 1;
    const int lane = tid & 31;
    const int warp = tid >> 5;

    // Closed-form swizzle bases (i ^ ((i>>4)&15)):
    const int baseLO  = (tid << 4) | (tid & 15);
    const int baseMID = ((tid >> 4) << 8) | (tid & 15);
    const int baseHI  = tid ^ ((tid >> 4) & 15);

    // ---- angles for both items; W tile loaded once ----
    const float4 xA = __ldg(reinterpret_cast<const float4*>(x + bA * INDIM) + (tid & 63));
    const float4 xB = __ldg(reinterpret_cast<const float4*>(x + bB * INDIM) + (tid & 63));
    const int grp = tid >> 6;     // 0..3
#pragma unroll
    for (int it = 0; it < 3; it++) {
        const int w = it * 4 + grp;
        float4 wv = __ldg(reinterpret_cast<const float4*>(W + w * INDIM) + (tid & 63));
        float pA = fmaf(xA.x, wv.x, fmaf(xA.y, wv.y, fmaf(xA.z, wv.z, xA.w * wv.w)));
        float pB = fmaf(xB.x, wv.x, fmaf(xB.y, wv.y, fmaf(xB.z, wv.z, xB.w * wv.w)));
#pragma unroll
        for (int o = 16; o > 0; o >>= 1) {
            pA += __shfl_xor_sync(0xffffffffu, pA, o);
            pB += __shfl_xor_sync(0xffffffffu, pB, o);
        }
        if (lane == 0) {
            red[0][w * 2 + (warp & 1)] = pA;
            red[1][w * 2 + (warp & 1)] = pB;
        }
    }
    __syncthreads();

    // ---- merged Walsh coefficients; item A on threads 0..11, item B on 32..43 ----
    {
        int itm = -1, v = 0;
        if (tid < NW)                        { itm = 0; v = tid; }
        else if (tid >= 32 && tid < 32 + NW) { itm = 1; v = tid - 32; }
        if (itm >= 0) {
            float a = red[itm][v * 2] + red[itm][v * 2 + 1];
            float* cvp = cv[itm];
            if (v <= 9) {
                cvp[v * 4 + 0] = -0.5f * (a + params[v]);      // P=0x111 (init+depth0)
                cvp[v * 4 + 1] = -0.5f * params[NW + v];       // P=0x333
                cvp[v * 4 + 2] = -0.5f * params[2 * NW + v];   // P=0x555
                cvp[v * 4 + 3] = -0.5f * params[3 * NW + v];   // P=0xFFF
            } else if (v == 10) {
                cvp[40] = -0.5f * (a + params[10] + params[2 * NW + 10]);   // mask 0x400
                cvp[41] = -0.5f * (params[NW + 10] + params[3 * NW + 10]);  // mask 0xC00
            } else {
                cvp[42] = -0.5f * (a + params[11] + params[NW + 11]
                                  + params[2 * NW + 11] + params[3 * NW + 11]); // 0x800
            }
        }
    }
    __syncthreads();

    // ---- sign words (tid-only, shared by both items) ----
    const uint32_t T12 = (uint32_t)tid << 4;
    const uint32_t w1v = T12 ^ (T12 >> 4) ^ (T12 >> 8);
    const uint32_t w3v = w1v ^ (w1v >> 1);
    const uint32_t wArr[4] = {w1v, w3v, w1v ^ (w1v >> 2), w3v ^ (w3v >> 2)};

    uint64_t UA[16], UB[16];
    phase_to_unit(cv[0], (uint32_t)tid, wArr, UA);
    phase_to_unit(cv[1], (uint32_t)tid, wArr, UB);

    // ---- complex WHT: packed butterflies, LO -> MID -> HI, both items ----
    wht16p(UA); wht16p(UB);
#pragma unroll
    for (int g = 0; g < 16; g++) { csA[baseLO ^ g] = UA[g]; csB[baseLO ^ g] = UB[g]; }
    __syncthreads();
#pragma unroll
    for (int g = 0; g < 16; g++) { UA[g] = csA[baseMID ^ (17 * g)]; UB[g] = csB[baseMID ^ (17 * g)]; }
    wht16p(UA); wht16p(UB);
#pragma unroll
    for (int g = 0; g < 16; g++) { csA[baseMID ^ (17 * g)] = UA[g]; csB[baseMID ^ (17 * g)] = UB[g]; }
    __syncthreads();
#pragma unroll
    for (int g = 0; g < 16; g++) { UA[g] = csA[baseHI + (g << 8)]; UB[g] = csB[baseHI + (g << 8)]; }
    wht16p(UA); wht16p(UB);

    // ---- Parseval ----
    float psA, A8, A9, A10, A11;
    float psB, B8, B9, B10, B11;
    parseval(UA, psA, A8, A9, A10, A11);
    parseval(UB, psB, B8, B9, B10, B11);

    // ---- Warp-WHT on psum (both items) ----
    {
        float vA = psA, vB = psB;
#pragma unroll
        for (int o = 1; o < 32; o <<= 1) {
            float rA = __shfl_xor_sync(0xffffffffu, vA, o);
            float rB = __shfl_xor_sync(0xffffffffu, vB, o);
            vA = (lane & o) ? (rA - vA) : (vA + rA);
            vB = (lane & o) ? (rB - vB) : (vB + rB);
        }
        if (lane == 0) { w0[0][warp] = vA; w0[1][warp] = vB; }
        else if ((lane & (lane - 1)) == 0) {
            wA[0][__popc(lane - 1) * 8 + warp] = vA;
            wA[1][__popc(lane - 1) * 8 + warp] = vB;
        }
    }
    // T8..T11 both items: 3 shfl levels, lanes 0..3 store group sums
    {
#pragma unroll
        for (int o = 16; o >= 4; o >>= 1) {
            A8 += __shfl_xor_sync(0xffffffffu, A8, o);  A9 += __shfl_xor_sync(0xffffffffu, A9, o);
            A10 += __shfl_xor_sync(0xffffffffu, A10, o); A11 += __shfl_xor_sync(0xffffffffu, A11, o);
            B8 += __shfl_xor_sync(0xffffffffu, B8, o);  B9 += __shfl_xor_sync(0xffffffffu, B9, o);
            B10 += __shfl_xor_sync(0xffffffffu, B10, o); B11 += __shfl_xor_sync(0xffffffffu, B11, o);
        }
        if (lane < 4) {
            const int idx = warp * 4 + lane;
            wT[0][0 * 32 + idx] = A8;  wT[0][1 * 32 + idx] = A9;
            wT[0][2 * 32 + idx] = A10; wT[0][3 * 32 + idx] = A11;
            wT[1][0 * 32 + idx] = B8;  wT[1][1 * 32 + idx] = B9;
            wT[1][2 * 32 + idx] = B10; wT[1][3 * 32 + idx] = B11;
        }
    }
    __syncthreads();

    // ---- final combine; item A on threads 0..11, item B on 32..43 ----
    {
        int itm = -1, w = 0;
        if (tid < NW)                        { itm = 0; w = tid; }
        else if (tid >= 32 && tid < 32 + NW) { itm = 1; w = tid - 32; }
        if (itm >= 0) {
            float t = 0.f;
            if (w < 5) {
#pragma unroll
                for (int k = 0; k < 8; k++) t += wA[itm][w * 8 + k];
            } else if (w < 8) {
#pragma unroll
                for (int k = 0; k < 8; k++)
                    t += ((k >> (w - 5)) & 1) ? -w0[itm][k] : w0[itm][k];
            } else {
#pragma unroll
                for (int j = 0; j < 32; j++) t += wT[itm][(w - 8) * 32 + j];
            }
            const int bb = (itm == 0) ? bA : bB;
            out[bb * NW + w] = t * (1.f / 16777216.f);   // 2^-24
        }
    }
}

extern "C" void kernel_launch(void* const* d_in, const int* in_sizes, int n_in,
                              void* d_out, int out_size)
{
    // Identify inputs by element count — robust to metadata ordering.
    const float* x = nullptr;      // 4096*256 = 1048576
    const float* W = nullptr;      // 12*256   = 3072
    const float* params = nullptr; // 4*12*1   = 48
    for (int i = 0; i < n_in; i++) {
        if      (in_sizes[i] == 4096 * 256) x      = (const float*)d_in[i];
        else if (in_sizes[i] == 12 * 256)   W      = (const float*)d_in[i];
        else if (in_sizes[i] == 48)         params = (const float*)d_in[i];
    }
    static bool attr_set = false;
    if (!attr_set) {
        cudaFuncSetAttribute(sim_kernel, cudaFuncAttributeMaxDynamicSharedMemorySize,
                             2 * DIM * 8);
        attr_set = true;
    }
    sim_kernel<<<2048, NT, 2 * DIM * 8>>>(x, W, params, (float*)d_out);
}